// round 6
// baseline (speedup 1.0000x reference)
#include <cuda_runtime.h>

#define N_NODES  50000
#define N_EDGES  800000
#define N_GRAPHS 64
#define HID      64

// ---------------- scratch (device globals; no allocation) ----------------
__device__ int   g_in_deg[N_NODES];
__device__ int   g_out_deg[N_NODES];
__device__ float g_norm_src[N_NODES];
__device__ float g_norm_dst[N_NODES];
__device__ float g_h0[N_NODES];
__device__ int   g_row_off[N_NODES + 1];
__device__ int   g_cursor[N_NODES];
__device__ int   g_edge_src[N_EDGES];
__device__ float g_hA[N_NODES * HID];
__device__ float g_hB[N_NODES * HID];
__device__ float g_hg[N_GRAPHS * HID];
__device__ float g_cnt[N_GRAPHS];

// ---------------- init / degrees / norms ----------------
__global__ void k_zero() {
    int i = blockIdx.x * blockDim.x + threadIdx.x;
    if (i < N_NODES) { g_in_deg[i] = 0; g_out_deg[i] = 0; }
    if (i < N_GRAPHS * HID) g_hg[i] = 0.f;
    if (i < N_GRAPHS) g_cnt[i] = 0.f;
}

__global__ void k_deg(const int* __restrict__ src, const int* __restrict__ dst) {
    int i = blockIdx.x * blockDim.x + threadIdx.x;
    if (i < N_EDGES) {
        atomicAdd(&g_in_deg[dst[i]], 1);
        atomicAdd(&g_out_deg[src[i]], 1);
    }
}

__global__ void k_norm() {
    int i = blockIdx.x * blockDim.x + threadIdx.x;
    if (i < N_NODES) {
        int id = g_in_deg[i], od = g_out_deg[i];
        g_norm_dst[i] = rsqrtf((float)(id > 1 ? id : 1));
        g_norm_src[i] = rsqrtf((float)(od > 1 ? od : 1));
        g_h0[i] = (float)id;
    }
}

// ---------------- single-block exclusive scan of in_deg -> row_off ----------------
#define SCAN_T 1024
#define SCAN_ITEMS ((N_NODES + SCAN_T - 1) / SCAN_T)   // 49

__global__ void k_scan() {
    __shared__ int sums[SCAN_T];
    int t = threadIdx.x;
    int base = t * SCAN_ITEMS;

    int local = 0;
    #pragma unroll
    for (int i = 0; i < SCAN_ITEMS; i++) {
        int idx = base + i;
        if (idx < N_NODES) local += g_in_deg[idx];
    }
    sums[t] = local;
    __syncthreads();

    // Hillis-Steele inclusive scan
    for (int off = 1; off < SCAN_T; off <<= 1) {
        int v = 0;
        if (t >= off) v = sums[t - off];
        __syncthreads();
        if (t >= off) sums[t] += v;
        __syncthreads();
    }

    int run = (t == 0) ? 0 : sums[t - 1];  // exclusive prefix of this chunk
    #pragma unroll
    for (int i = 0; i < SCAN_ITEMS; i++) {
        int idx = base + i;
        if (idx < N_NODES) {
            g_row_off[idx] = run;
            g_cursor[idx]  = run;
            run += g_in_deg[idx];
        }
    }
    if (t == 0) g_row_off[N_NODES] = sums[SCAN_T - 1];
}

// ---------------- bucket edges by dst ----------------
__global__ void k_bucket(const int* __restrict__ src, const int* __restrict__ dst) {
    int i = blockIdx.x * blockDim.x + threadIdx.x;
    if (i < N_EDGES) {
        int d = dst[i];
        int p = atomicAdd(&g_cursor[d], 1);
        g_edge_src[p] = src[i];
    }
}

// ---------------- layer 0: scalar aggregate -> outer product with W0 ----------------
__global__ void k_layer0(const float* __restrict__ W0, const float* __restrict__ b0) {
    int gtid = blockIdx.x * blockDim.x + threadIdx.x;
    int v = gtid >> 5;
    int lane = gtid & 31;
    if (v >= N_NODES) return;

    int beg = g_row_off[v], end = g_row_off[v + 1];
    float acc = 0.f;
    for (int e = beg + lane; e < end; e += 32) {
        int s = g_edge_src[e];
        acc += g_h0[s] * g_norm_src[s];
    }
    #pragma unroll
    for (int off = 16; off; off >>= 1) acc += __shfl_xor_sync(0xffffffffu, acc, off);

    float x = acc * g_norm_dst[v];
    float2 w = *(const float2*)&W0[2 * lane];
    float2 bb = *(const float2*)&b0[2 * lane];
    float2 o;
    o.x = fmaxf(fmaf(x, w.x, bb.x), 0.f);
    o.y = fmaxf(fmaf(x, w.y, bb.y), 0.f);
    *(float2*)&g_hA[v * HID + 2 * lane] = o;
}

// ---------------- feature layer: gather-aggregate + fused 64x64 matvec + relu ----------------
// warp per node; lane owns features (2*lane, 2*lane+1). dir=0: hA->hB, dir=1: hB->hA
__global__ void __launch_bounds__(256) k_layer(const float* __restrict__ W,
                                               const float* __restrict__ b,
                                               int dir) {
    __shared__ float sW[HID * HID];
    __shared__ float sb[HID];
    __shared__ float xs[8][HID];

    const float* hin  = dir ? g_hB : g_hA;
    float*       hout = dir ? g_hA : g_hB;

    int tid = threadIdx.x;
    for (int i = tid; i < HID * HID; i += 256) sW[i] = W[i];
    if (tid < HID) sb[tid] = b[tid];
    __syncthreads();

    int wib = tid >> 5;
    int lane = tid & 31;
    int v = blockIdx.x * 8 + wib;

    if (v < N_NODES) {
        int beg = g_row_off[v], end = g_row_off[v + 1];
        float a0 = 0.f, a1 = 0.f;
        for (int e = beg; e < end; e++) {
            int s = g_edge_src[e];
            float ns = g_norm_src[s];
            float2 hv = *(const float2*)&hin[s * HID + 2 * lane];
            a0 = fmaf(hv.x, ns, a0);
            a1 = fmaf(hv.y, ns, a1);
        }
        float nd = g_norm_dst[v];
        xs[wib][2 * lane]     = a0 * nd;
        xs[wib][2 * lane + 1] = a1 * nd;
    }
    __syncwarp();

    if (v < N_NODES) {
        float o0 = sb[2 * lane], o1 = sb[2 * lane + 1];
        #pragma unroll
        for (int i = 0; i < HID; i++) {
            float xi = xs[wib][i];
            float2 w = *(const float2*)&sW[i * HID + 2 * lane];
            o0 = fmaf(xi, w.x, o0);
            o1 = fmaf(xi, w.y, o1);
        }
        float2 o;
        o.x = fmaxf(o0, 0.f);
        o.y = fmaxf(o1, 0.f);
        *(float2*)&hout[v * HID + 2 * lane] = o;
    }
}

// ---------------- graph pooling (mean) ----------------
__global__ void k_pool(const int* __restrict__ n2g) {
    int gtid = blockIdx.x * blockDim.x + threadIdx.x;
    int v = gtid >> 5;
    int lane = gtid & 31;
    if (v >= N_NODES) return;
    int g = n2g[v];
    float2 hv = *(const float2*)&g_hA[v * HID + 2 * lane];
    atomicAdd(&g_hg[g * HID + 2 * lane], hv.x);
    atomicAdd(&g_hg[g * HID + 2 * lane + 1], hv.y);
    if (lane == 0) atomicAdd(&g_cnt[g], 1.f);
}

// ---------------- readout ----------------
__global__ void k_out(const float* __restrict__ Wr, const float* __restrict__ br,
                      float* __restrict__ out) {
    int gtid = blockIdx.x * blockDim.x + threadIdx.x;
    int g = gtid >> 5;
    int lane = gtid & 31;
    if (g >= N_GRAPHS) return;
    float inv = 1.f / fmaxf(g_cnt[g], 1.f);
    float2 hv = *(const float2*)&g_hg[g * HID + 2 * lane];
    float2 wr = *(const float2*)&Wr[2 * lane];
    float acc = hv.x * inv * wr.x + hv.y * inv * wr.y;
    #pragma unroll
    for (int off = 16; off; off >>= 1) acc += __shfl_xor_sync(0xffffffffu, acc, off);
    if (lane == 0) out[g] = acc + br[0];
}

// ---------------- launch ----------------
extern "C" void kernel_launch(void* const* d_in, const int* in_sizes, int n_in,
                              void* d_out, int out_size) {
    const int*   src = (const int*)d_in[0];
    const int*   dst = (const int*)d_in[1];
    const int*   n2g = (const int*)d_in[2];
    const float* W0  = (const float*)d_in[3];
    const float* b0  = (const float*)d_in[4];
    const float* W1  = (const float*)d_in[5];
    const float* b1  = (const float*)d_in[6];
    const float* W2  = (const float*)d_in[7];
    const float* b2  = (const float*)d_in[8];
    const float* Wr  = (const float*)d_in[9];
    const float* br  = (const float*)d_in[10];
    float* out = (float*)d_out;

    const int TB = 256;
    k_zero  <<<(N_NODES + TB - 1) / TB, TB>>>();
    k_deg   <<<(N_EDGES + TB - 1) / TB, TB>>>(src, dst);
    k_norm  <<<(N_NODES + TB - 1) / TB, TB>>>();
    k_scan  <<<1, SCAN_T>>>();
    k_bucket<<<(N_EDGES + TB - 1) / TB, TB>>>(src, dst);

    k_layer0<<<(N_NODES * 32 + TB - 1) / TB, TB>>>(W0, b0);
    k_layer <<<(N_NODES + 7) / 8, TB>>>(W1, b1, 0);  // hA -> hB
    k_layer <<<(N_NODES + 7) / 8, TB>>>(W2, b2, 1);  // hB -> hA

    k_pool  <<<(N_NODES * 32 + TB - 1) / TB, TB>>>(n2g);
    k_out   <<<(N_GRAPHS * 32 + TB - 1) / TB, TB>>>(Wr, br, out);
}

// round 8
// speedup vs baseline: 1.3546x; 1.3546x over previous
#include <cuda_runtime.h>

#define N_NODES  50000
#define N_EDGES  800000
#define N_GRAPHS 64
#define HID      64

#define CHUNK 256
#define NBLK ((N_NODES + CHUNK - 1) / CHUNK)   // 196

// ---------------- scratch (device globals; no allocation) ----------------
__device__ int   g_in_deg[N_NODES];
__device__ int   g_out_deg[N_NODES];
__device__ float g_norm_src[N_NODES];
__device__ float g_norm_dst[N_NODES];
__device__ float g_h0[N_NODES];
__device__ int   g_row_off[N_NODES + 1];
__device__ int   g_cursor[N_NODES];
__device__ int   g_edge_src[N_EDGES];
__device__ float g_hA[N_NODES * HID];
__device__ float g_hB[N_NODES * HID];
__device__ float g_hg[N_GRAPHS * HID];
__device__ float g_cnt[N_GRAPHS];
__device__ int   g_part[NBLK];
__device__ int   g_partoff[NBLK];

// ---------------- init / degrees / norms ----------------
__global__ void k_zero() {
    int i = blockIdx.x * blockDim.x + threadIdx.x;
    if (i < N_NODES) { g_in_deg[i] = 0; g_out_deg[i] = 0; }
    if (i < N_GRAPHS * HID) g_hg[i] = 0.f;
    if (i < N_GRAPHS) g_cnt[i] = 0.f;
}

__global__ void k_deg(const int* __restrict__ src, const int* __restrict__ dst) {
    int i = blockIdx.x * blockDim.x + threadIdx.x;
    if (i < N_EDGES) {
        atomicAdd(&g_in_deg[dst[i]], 1);
        atomicAdd(&g_out_deg[src[i]], 1);
    }
}

__global__ void k_norm() {
    int i = blockIdx.x * blockDim.x + threadIdx.x;
    if (i < N_NODES) {
        int id = g_in_deg[i], od = g_out_deg[i];
        g_norm_dst[i] = rsqrtf((float)(id > 1 ? id : 1));
        g_norm_src[i] = rsqrtf((float)(od > 1 ? od : 1));
        g_h0[i] = (float)id;
    }
}

// ---------------- coalesced two-level exclusive scan of in_deg ----------------
// Level 1: per-block sums (coalesced, one element per thread)
__global__ void k_partial() {
    __shared__ int s[CHUNK];
    int t = threadIdx.x;
    int idx = blockIdx.x * CHUNK + t;
    s[t] = (idx < N_NODES) ? g_in_deg[idx] : 0;
    __syncthreads();
    #pragma unroll
    for (int off = CHUNK / 2; off > 0; off >>= 1) {
        if (t < off) s[t] += s[t + off];
        __syncthreads();
    }
    if (t == 0) g_part[blockIdx.x] = s[0];
}

// Level 2: scan the NBLK partials (single tiny block)
__global__ void k_scanpart() {
    __shared__ int s[CHUNK];
    int t = threadIdx.x;
    s[t] = (t < NBLK) ? g_part[t] : 0;
    __syncthreads();
    #pragma unroll
    for (int off = 1; off < CHUNK; off <<= 1) {
        int v = (t >= off) ? s[t - off] : 0;
        __syncthreads();
        s[t] += v;
        __syncthreads();
    }
    if (t < NBLK) g_partoff[t] = (t == 0) ? 0 : s[t - 1];   // exclusive
    if (t == 0) g_row_off[N_NODES] = N_EDGES;               // total is known
}

// Level 3: per-block exclusive scan + block prefix (coalesced in & out)
__global__ void k_offsets() {
    __shared__ int s[CHUNK];
    int t = threadIdx.x;
    int idx = blockIdx.x * CHUNK + t;
    int my = (idx < N_NODES) ? g_in_deg[idx] : 0;
    s[t] = my;
    __syncthreads();
    #pragma unroll
    for (int off = 1; off < CHUNK; off <<= 1) {
        int v = (t >= off) ? s[t - off] : 0;
        __syncthreads();
        s[t] += v;
        __syncthreads();
    }
    if (idx < N_NODES) {
        int ex = s[t] - my + g_partoff[blockIdx.x];   // exclusive prefix
        g_row_off[idx] = ex;
        g_cursor[idx]  = ex;
    }
}

// ---------------- bucket edges by dst ----------------
__global__ void k_bucket(const int* __restrict__ src, const int* __restrict__ dst) {
    int i = blockIdx.x * blockDim.x + threadIdx.x;
    if (i < N_EDGES) {
        int d = dst[i];
        int p = atomicAdd(&g_cursor[d], 1);
        g_edge_src[p] = src[i];
    }
}

// ---------------- layer 0: scalar aggregate -> outer product with W0 ----------------
__global__ void k_layer0(const float* __restrict__ W0, const float* __restrict__ b0) {
    int gtid = blockIdx.x * blockDim.x + threadIdx.x;
    int v = gtid >> 5;
    int lane = gtid & 31;
    if (v >= N_NODES) return;

    int beg = g_row_off[v], end = g_row_off[v + 1];
    float acc = 0.f;
    for (int e = beg + lane; e < end; e += 32) {
        int s = g_edge_src[e];
        acc += g_h0[s] * g_norm_src[s];
    }
    #pragma unroll
    for (int off = 16; off; off >>= 1) acc += __shfl_xor_sync(0xffffffffu, acc, off);

    float x = acc * g_norm_dst[v];
    float2 w = *(const float2*)&W0[2 * lane];
    float2 bb = *(const float2*)&b0[2 * lane];
    float2 o;
    o.x = fmaxf(fmaf(x, w.x, bb.x), 0.f);
    o.y = fmaxf(fmaf(x, w.y, bb.y), 0.f);
    *(float2*)&g_hA[v * HID + 2 * lane] = o;
}

// ---------------- feature layer: gather-aggregate + fused 64x64 matvec + relu ----------------
// warp per node; lane owns features (2*lane, 2*lane+1). dir=0: hA->hB, dir=1: hB->hA
__global__ void __launch_bounds__(256) k_layer(const float* __restrict__ W,
                                               const float* __restrict__ b,
                                               int dir) {
    __shared__ float sW[HID * HID];
    __shared__ float sb[HID];
    __shared__ float xs[8][HID];

    const float* hin  = dir ? g_hB : g_hA;
    float*       hout = dir ? g_hA : g_hB;

    int tid = threadIdx.x;
    for (int i = tid; i < HID * HID; i += 256) sW[i] = W[i];
    if (tid < HID) sb[tid] = b[tid];
    __syncthreads();

    int wib = tid >> 5;
    int lane = tid & 31;
    int v = blockIdx.x * 8 + wib;

    if (v < N_NODES) {
        int beg = g_row_off[v], end = g_row_off[v + 1];
        float a0 = 0.f, a1 = 0.f;
        for (int e = beg; e < end; e++) {
            int s = g_edge_src[e];
            float ns = g_norm_src[s];
            float2 hv = *(const float2*)&hin[s * HID + 2 * lane];
            a0 = fmaf(hv.x, ns, a0);
            a1 = fmaf(hv.y, ns, a1);
        }
        float nd = g_norm_dst[v];
        xs[wib][2 * lane]     = a0 * nd;
        xs[wib][2 * lane + 1] = a1 * nd;
    }
    __syncwarp();

    if (v < N_NODES) {
        float o0 = sb[2 * lane], o1 = sb[2 * lane + 1];
        #pragma unroll
        for (int i = 0; i < HID; i++) {
            float xi = xs[wib][i];
            float2 w = *(const float2*)&sW[i * HID + 2 * lane];
            o0 = fmaf(xi, w.x, o0);
            o1 = fmaf(xi, w.y, o1);
        }
        float2 o;
        o.x = fmaxf(o0, 0.f);
        o.y = fmaxf(o1, 0.f);
        *(float2*)&hout[v * HID + 2 * lane] = o;
    }
}

// ---------------- graph pooling (mean) ----------------
__global__ void k_pool(const int* __restrict__ n2g) {
    int gtid = blockIdx.x * blockDim.x + threadIdx.x;
    int v = gtid >> 5;
    int lane = gtid & 31;
    if (v >= N_NODES) return;
    int g = n2g[v];
    float2 hv = *(const float2*)&g_hA[v * HID + 2 * lane];
    atomicAdd(&g_hg[g * HID + 2 * lane], hv.x);
    atomicAdd(&g_hg[g * HID + 2 * lane + 1], hv.y);
    if (lane == 0) atomicAdd(&g_cnt[g], 1.f);
}

// ---------------- readout ----------------
__global__ void k_out(const float* __restrict__ Wr, const float* __restrict__ br,
                      float* __restrict__ out) {
    int gtid = blockIdx.x * blockDim.x + threadIdx.x;
    int g = gtid >> 5;
    int lane = gtid & 31;
    if (g >= N_GRAPHS) return;
    float inv = 1.f / fmaxf(g_cnt[g], 1.f);
    float2 hv = *(const float2*)&g_hg[g * HID + 2 * lane];
    float2 wr = *(const float2*)&Wr[2 * lane];
    float acc = hv.x * inv * wr.x + hv.y * inv * wr.y;
    #pragma unroll
    for (int off = 16; off; off >>= 1) acc += __shfl_xor_sync(0xffffffffu, acc, off);
    if (lane == 0) out[g] = acc + br[0];
}

// ---------------- launch ----------------
extern "C" void kernel_launch(void* const* d_in, const int* in_sizes, int n_in,
                              void* d_out, int out_size) {
    const int*   src = (const int*)d_in[0];
    const int*   dst = (const int*)d_in[1];
    const int*   n2g = (const int*)d_in[2];
    const float* W0  = (const float*)d_in[3];
    const float* b0  = (const float*)d_in[4];
    const float* W1  = (const float*)d_in[5];
    const float* b1  = (const float*)d_in[6];
    const float* W2  = (const float*)d_in[7];
    const float* b2  = (const float*)d_in[8];
    const float* Wr  = (const float*)d_in[9];
    const float* br  = (const float*)d_in[10];
    float* out = (float*)d_out;

    const int TB = 256;
    k_zero    <<<(N_NODES + TB - 1) / TB, TB>>>();
    k_deg     <<<(N_EDGES + TB - 1) / TB, TB>>>(src, dst);
    k_norm    <<<(N_NODES + TB - 1) / TB, TB>>>();
    k_partial <<<NBLK, CHUNK>>>();
    k_scanpart<<<1, CHUNK>>>();
    k_offsets <<<NBLK, CHUNK>>>();
    k_bucket  <<<(N_EDGES + TB - 1) / TB, TB>>>(src, dst);

    k_layer0<<<(N_NODES * 32 + TB - 1) / TB, TB>>>(W0, b0);
    k_layer <<<(N_NODES + 7) / 8, TB>>>(W1, b1, 0);  // hA -> hB
    k_layer <<<(N_NODES + 7) / 8, TB>>>(W2, b2, 1);  // hB -> hA

    k_pool  <<<(N_NODES * 32 + TB - 1) / TB, TB>>>(n2g);
    k_out   <<<(N_GRAPHS * 32 + TB - 1) / TB, TB>>>(Wr, br, out);
}